// round 7
// baseline (speedup 1.0000x reference)
#include <cuda_runtime.h>
#include <math.h>

#define Bn 16
#define Cn 3
#define Hn 512
#define Wn 512
#define HW (Hn * Wn)           // 262144
#define CHW (Cn * HW)          // 786432
#define NTOT (Bn * Cn * HW)    // 12582912

#define TW 64                  // owned tile width
#define TH 32                  // owned tile height
#define HTW 72                 // halo smem width: cols [w0-4, w0+67], float4-aligned
#define HTH (TH + 2)           // 34
#define VPR (HTW / 4)          // 18 float4 vectors per halo row
#define NITEMS (HTH * VPR)     // 612
#define NTHREADS 256

#define GX (Wn / TW)           // 8
#define GY (Hn / TH)           // 16
#define BPB (GX * GY)          // 128 blocks per batch image
#define NBLK (BPB * Bn)        // 2048

// Per-block float partials (RAW scale, deferred 1/255), written exactly once.
// [0]=sum(r_raw), [1]=sum(r_raw^2), [2]=sum(|lv_raw|*r_raw*mask)
__device__ float g_part[3][NBLK];
__device__ unsigned int g_count;   // zero-init; last block resets to 0

__device__ __forceinline__ int reflect(int i, int n) {
    return (i < 0) ? -i : ((i >= n) ? 2 * n - 2 - i : i);
}

// Compute one float4 of signed raw residuals into the smem tile.
__device__ __forceinline__ void make_tile_vec(
    float* rt, int t, int w0, int h0, int base,
    const float* __restrict__ sr, const float* __restrict__ srema,
    const float* __restrict__ hr)
{
    const int ty  = t / VPR;
    const int v   = t - ty * VPR;
    const int gh  = reflect(h0 - 1 + ty, Hn);
    const int gw0 = w0 - 4 + 4 * v;
    float4 o4;
    if (gw0 >= 0 && gw0 + 3 < Wn) {
        const int ix = base + gh * Wn + gw0;
        float4 rs4 = make_float4(0.f, 0.f, 0.f, 0.f);
        float4 re4 = make_float4(0.f, 0.f, 0.f, 0.f);
#pragma unroll
        for (int c = 0; c < Cn; ++c) {
            const int o = ix + c * HW;
            float4 h4 = __ldg((const float4*)(hr    + o));
            float4 s4 = __ldg((const float4*)(sr    + o));
            float4 e4 = __ldg((const float4*)(srema + o));
            rs4.x += fabsf(h4.x - s4.x); re4.x += fabsf(h4.x - e4.x);
            rs4.y += fabsf(h4.y - s4.y); re4.y += fabsf(h4.y - e4.y);
            rs4.z += fabsf(h4.z - s4.z); re4.z += fabsf(h4.z - e4.z);
            rs4.w += fabsf(h4.w - s4.w); re4.w += fabsf(h4.w - e4.w);
        }
        // rs<re is scale-invariant: no 1/255 here (deferred to finalize)
        o4.x = (rs4.x < re4.x) ? __int_as_float(__float_as_int(rs4.x) | 0x80000000u) : rs4.x;
        o4.y = (rs4.y < re4.y) ? __int_as_float(__float_as_int(rs4.y) | 0x80000000u) : rs4.y;
        o4.z = (rs4.z < re4.z) ? __int_as_float(__float_as_int(rs4.z) | 0x80000000u) : rs4.z;
        o4.w = (rs4.w < re4.w) ? __int_as_float(__float_as_int(rs4.w) | 0x80000000u) : rs4.w;
    } else {
        float vals[4];
#pragma unroll
        for (int e = 0; e < 4; ++e) {
            const int gw = reflect(gw0 + e, Wn);
            const int ix = base + gh * Wn + gw;
            float rs = 0.f, re = 0.f;
#pragma unroll
            for (int c = 0; c < Cn; ++c) {
                float h  = __ldg(hr    + ix + c * HW);
                float s  = __ldg(sr    + ix + c * HW);
                float se = __ldg(srema + ix + c * HW);
                rs += fabsf(h - s);
                re += fabsf(h - se);
            }
            vals[e] = (rs < re) ? __int_as_float(__float_as_int(rs) | 0x80000000u) : rs;
        }
        o4 = make_float4(vals[0], vals[1], vals[2], vals[3]);
    }
    *(float4*)(rt + ty * HTW + 4 * v) = o4;
}

// ---------------------------------------------------------------------------
__global__ __launch_bounds__(NTHREADS, 8) void fused_kernel(
    const float* __restrict__ sr,
    const float* __restrict__ srema,
    const float* __restrict__ hr,
    float* __restrict__ out)
{
    __shared__ float rt[HTH * HTW];     // signed raw residual tile

    const int tid = threadIdx.x;
    const int w0  = blockIdx.x * TW;
    const int h0  = blockIdx.y * TH;
    const int b   = blockIdx.z;
    const int base = b * CHW;

    // --- Phase 1: halo tile (612 items = 2 full passes + 100 tail) ----------
    make_tile_vec(rt, tid,       w0, h0, base, sr, srema, hr);
    make_tile_vec(rt, tid + 256, w0, h0, base, sr, srema, hr);
    if (tid < NITEMS - 512)
        make_tile_vec(rt, tid + 512, w0, h0, base, sr, srema, hr);
    __syncthreads();

    // --- Phase 2: sliding-window 3x3 variance, 1 col x 8 rows per thread ----
    // Thread owns col c (0..63), rows row0..row0+7 (row0 = (tid>>6)*8).
    const int c    = tid & 63;
    const int row0 = (tid >> 6) * 8;
    const float* cp = rt + (row0 * HTW) + c + 3;   // window-left col, top halo row

    float lsum = 0.f, lsq = 0.f, lS = 0.f;

    // preload halo rows row0 (prev) and row0+1 (cur = center of owned row0)
    float vl = cp[0], vc = cp[1], vr = cp[2];
    float a_prev = fabsf(vl) + fabsf(vc) + fabsf(vr);
    float b_prev = vl * vl + vc * vc + vr * vr;
    cp += HTW;
    vl = cp[0]; vc = cp[1]; vr = cp[2];
    float a_cur = fabsf(vl) + fabsf(vc) + fabsf(vr);
    float b_cur = vl * vl + vc * vc + vr * vr;
    float cen   = vc;                               // signed center, owned row0

#pragma unroll
    for (int j = 0; j < 8; ++j) {
        cp += HTW;
        vl = cp[0]; vc = cp[1]; vr = cp[2];
        float a_next = fabsf(vl) + fabsf(vc) + fabsf(vr);
        float b_next = vl * vl + vc * vc + vr * vr;

        float s  = a_prev + a_cur + a_next;
        float sq = b_prev + b_cur + b_next;
        float lv = (sq - s * s * (1.0f / 9.0f)) * (1.0f / 8.0f);

        float r4 = fabsf(cen);
        lS   += signbit(cen) ? 0.0f : fabsf(lv) * r4;
        lsum += r4;
        lsq  += r4 * r4;

        a_prev = a_cur; b_prev = b_cur;
        a_cur = a_next; b_cur = b_next;
        cen = vc;
    }

    // --- Block reduction -----------------------------------------------------
    __shared__ float wsum[8], wsq[8], wS[8];
#pragma unroll
    for (int o = 16; o > 0; o >>= 1) {
        lsum += __shfl_down_sync(0xffffffffu, lsum, o);
        lsq  += __shfl_down_sync(0xffffffffu, lsq,  o);
        lS   += __shfl_down_sync(0xffffffffu, lS,   o);
    }
    const int warp = tid >> 5;
    if ((tid & 31) == 0) { wsum[warp] = lsum; wsq[warp] = lsq; wS[warp] = lS; }
    __syncthreads();

    __shared__ bool isLast;
    if (tid == 0) {
        float a = 0.f, cc = 0.f, d = 0.f;
#pragma unroll
        for (int i = 0; i < 8; ++i) { a += wsum[i]; cc += wsq[i]; d += wS[i]; }
        const int bid = blockIdx.x + GX * blockIdx.y + BPB * blockIdx.z;
        g_part[0][bid] = a;
        g_part[1][bid] = cc;
        g_part[2][bid] = d;
        __threadfence();
        unsigned prev = atomicAdd(&g_count, 1u);
        isLast = (prev == NBLK - 1);
    }
    __syncthreads();

    // --- Last block: per-batch patch weight + final loss ---------------------
    if (isLast) {
        if (tid == 0) g_count = 0;   // reset for next graph replay
        __shared__ float sres[Bn];
        const int warp2 = tid >> 5;
        const int lane  = tid & 31;
#pragma unroll
        for (int j = 0; j < 2; ++j) {
            const int bb  = warp2 * 2 + j;
            const int idx = bb * BPB + lane * 4;
            float s = 0.f, sq = 0.f, S = 0.f;
#pragma unroll
            for (int e = 0; e < 4; ++e) {
                s  += __ldcg(&g_part[0][idx + e]);
                sq += __ldcg(&g_part[1][idx + e]);
                S  += __ldcg(&g_part[2][idx + e]);
            }
#pragma unroll
            for (int o = 16; o > 0; o >>= 1) {
                s  += __shfl_down_sync(0xffffffffu, s,  o);
                sq += __shfl_down_sync(0xffffffffu, sq, o);
                S  += __shfl_down_sync(0xffffffffu, S,  o);
            }
            if (lane == 0) {
                const float n = (float)HW;
                float var = (sq - s * s / n) / (n - 1.0f);   // raw-scale variance
                float w = (var > 0.0f) ? exp2f(0.2f * log2f(var)) : 0.0f;
                sres[bb] = w * S;
            }
        }
        __syncthreads();
        if (tid == 0) {
            float acc = 0.f;
#pragma unroll
            for (int i = 0; i < Bn; ++i) acc += sres[i];
            // loss = 255/NTOT * sum_b (k^2 var)^0.2 * k^3 S  with k=1/255
            //      = 255^(-2.4)/NTOT * sum_b var_raw^0.2 * S_raw
            double Kd = pow(255.0, -2.4) / (double)NTOT;
            out[0] = (float)((double)acc * Kd);
        }
    }
}

// ---------------------------------------------------------------------------
extern "C" void kernel_launch(void* const* d_in, const int* in_sizes, int n_in,
                              void* d_out, int out_size) {
    const float* sr    = (const float*)d_in[0];
    const float* srema = (const float*)d_in[1];
    const float* hr    = (const float*)d_in[2];
    float* out = (float*)d_out;

    dim3 blk(NTHREADS, 1, 1);
    dim3 grd(GX, GY, Bn);
    fused_kernel<<<grd, blk>>>(sr, srema, hr, out);
}